// round 5
// baseline (speedup 1.0000x reference)
#include <cuda_runtime.h>
#include <cstdint>

// DynamicGraphModule_15144054686343
//
// Reference math reduces analytically:
//   scores[i,j] = row_term[i] + col_term[j] + b   (rank-1 + const)
//   adj = where(corr > 1.5, corr, 0)   -> {0} U (1.5, inf)
//   adj = where(adj < -1.5, adj, 0)    -> identically ZERO
//   out = adj @ (e @ W_gcn) + b_gcn    == broadcast(b_gcn) exactly
//
// Kernel: broadcast b_gcn [512] into out [1, 4096, 512] (8 MB fp32 stores).
//
// R4: TMA bulk-store variant. Each of 256 blocks stages 16 rows (32 KB) of the
// bias pattern in SMEM, then one cp.async.bulk shared->global moves the whole
// 32 KB. Global-store instruction count: 8192 warp STGs -> 256 TMA ops; the
// store stream runs on the TMA engine at the same LTS cap, bypassing the
// per-SM LSU/L1tex path entirely.

static constexpr int D_OUT       = 512;                 // floats per row
static constexpr int ROWS_PER_BLK = 16;
static constexpr int CHUNK_FLOATS = D_OUT * ROWS_PER_BLK;   // 8192 floats = 32 KB
static constexpr int CHUNK_BYTES  = CHUNK_FLOATS * 4;
static constexpr int N_BLOCKS     = 4096 / ROWS_PER_BLK;    // 256
static constexpr int THREADS      = 256;

__global__ void __launch_bounds__(THREADS)
broadcast_bias_tma_kernel(const float4* __restrict__ bias4,
                          float* __restrict__ out)
{
    __shared__ __align__(128) float smem[CHUNK_FLOATS];

    const int tid = threadIdx.x;
    float4* smem4 = reinterpret_cast<float4*>(smem);

    // Fill 32 KB of SMEM with the bias pattern (16 repeated rows).
    // 2048 float4 / 256 threads = 8 per thread; column phase = j & 127.
    const float4 b = bias4[tid & 127];
#pragma unroll
    for (int i = 0; i < CHUNK_FLOATS / 4 / THREADS; ++i) {
        smem4[tid + i * THREADS] = b;      // (tid + i*256) & 127 == tid & 127
    }
    __syncthreads();

    if (tid == 0) {
        // Make generic-proxy SMEM writes visible to the async (TMA) proxy.
        asm volatile("fence.proxy.async.shared::cta;" ::: "memory");

        uint32_t smem_addr;
        asm("{ .reg .u64 t; cvta.to.shared.u64 t, %1; cvt.u32.u64 %0, t; }"
            : "=r"(smem_addr) : "l"(smem));

        float* dst = out + (size_t)blockIdx.x * CHUNK_FLOATS;
        asm volatile(
            "cp.async.bulk.global.shared::cta.bulk_group [%0], [%1], %2;"
            :: "l"(dst), "r"(smem_addr), "n"(CHUNK_BYTES)
            : "memory");
        asm volatile("cp.async.bulk.commit_group;" ::: "memory");
        asm volatile("cp.async.bulk.wait_group 0;" ::: "memory");
    }
}

extern "C" void kernel_launch(void* const* d_in, const int* in_sizes, int n_in,
                              void* d_out, int out_size)
{
    // metadata order:
    // 0 spans_embeddings, 1 W_c1, 2 b_c1, 3 W_c2, 4 b_c2,
    // 5 W_link, 6 b_link, 7 W_gcn, 8 b_gcn
    const float4* bias4 = (const float4*)d_in[8];
    float* out = (float*)d_out;
    (void)in_sizes; (void)n_in; (void)out_size;   // out_size = 4096*512 exactly

    broadcast_bias_tma_kernel<<<N_BLOCKS, THREADS>>>(bias4, out);
}